// round 5
// baseline (speedup 1.0000x reference)
#include <cuda_runtime.h>
#include <cuda_bf16.h>

// LNN Euler-Lagrange residual: ReLU MLP => autodiff grad-of-grad vanishes;
// output is exactly -dL/dq (forward for masks + one backward).
//
// Round-5: f32x2 packing over the HIDDEN dim (no weight-dup movs) x
// 2 samples per thread (each broadcast LDS.128 feeds 4 independent fma2).
// Register arrays indexed only by compile-time constants; runtime loops
// touch only smem/global pointers. Persistent blocks amortize staging.

typedef unsigned long long u64;

__device__ __forceinline__ u64 pack2(float lo, float hi) {
    u64 d; asm("mov.b64 %0, {%1, %2};" : "=l"(d) : "f"(lo), "f"(hi)); return d;
}
__device__ __forceinline__ void unpack2(u64 v, float& lo, float& hi) {
    asm("mov.b64 {%0, %1}, %2;" : "=f"(lo), "=f"(hi) : "l"(v));
}
__device__ __forceinline__ u64 fma2(u64 a, u64 b, u64 c) {
    u64 d; asm("fma.rn.f32x2 %0, %1, %2, %3;" : "=l"(d) : "l"(a), "l"(b), "l"(c)); return d;
}
__device__ __forceinline__ u64 add2(u64 a, u64 b) {
    u64 d; asm("add.rn.f32x2 %0, %1, %2;" : "=l"(d) : "l"(a), "l"(b)); return d;
}

__global__ void __launch_bounds__(128, 3)
lnn_kernel(const float* __restrict__ X,
           const float* __restrict__ W1g, const float* __restrict__ b1g,
           const float* __restrict__ W2g, const float* __restrict__ b2g,
           const float* __restrict__ W3g,
           float* __restrict__ out, int B)
{
    __shared__ float sW1[4096];    // row i = W1[i,:]   (L1 accumulate; out dots)
    __shared__ float sW2T[4096];   // row j = W2[:,j]   (L2 sign dots; t accumulate)
    __shared__ float sb1[64], sb2[64], sW3[64];

    const int t = threadIdx.x;
    for (int i = t; i < 4096; i += 128) {
        sW1[i] = W1g[i];
        const int c = i >> 6, r = i & 63;
        sW2T[c * 64 + r] = W2g[r * 64 + c];   // coalesced STS, strided LDG
    }
    if (t < 64) { sb1[t] = b1g[t]; sb2[t] = b2g[t]; sW3[t] = W3g[t]; }
    __syncthreads();

    const int stride = gridDim.x * 256;       // 256 samples per block-iter
    for (int base = blockIdx.x * 256; base < B; base += stride) {
        const int sA = base + t;
        int sB = sA + 128;
        if (sA >= B) return;
        const bool bval = (sB < B);
        if (!bval) sB = sA;

        // ================ layer 1: h = relu(x @ W1 + b1) ===================
        u64 hA[32], hB[32];
        {
            const u64* bp = reinterpret_cast<const u64*>(sb1);
            #pragma unroll
            for (int p = 0; p < 32; p++) { u64 b = bp[p]; hA[p] = b; hB[p] = b; }
        }
        const float4* xAg = reinterpret_cast<const float4*>(X + (size_t)sA * 64);
        const float4* xBg = reinterpret_cast<const float4*>(X + (size_t)sB * 64);

        #pragma unroll 1
        for (int i4 = 0; i4 < 16; i4++) {
            const float4 vA = xAg[i4];
            const float4 vB = xBg[i4];
            const ulonglong2* row =
                reinterpret_cast<const ulonglong2*>(sW1 + i4 * 256);
            #pragma unroll
            for (int seg = 0; seg < 4; seg++) {
                const float fa = (seg == 0) ? vA.x : (seg == 1) ? vA.y
                                 : (seg == 2) ? vA.z : vA.w;
                const float fb = (seg == 0) ? vB.x : (seg == 1) ? vB.y
                                 : (seg == 2) ? vB.z : vB.w;
                const u64 xa = pack2(fa, fa);
                const u64 xb = pack2(fb, fb);
                const ulonglong2* rp = row + seg * 16;
                #pragma unroll
                for (int e = 0; e < 16; e++) {
                    const ulonglong2 w = rp[e];
                    hA[2*e]   = fma2(xa, w.x, hA[2*e]);
                    hA[2*e+1] = fma2(xa, w.y, hA[2*e+1]);
                    hB[2*e]   = fma2(xb, w.x, hB[2*e]);
                    hB[2*e+1] = fma2(xb, w.y, hB[2*e+1]);
                }
            }
        }

        // relu + layer-1 masks
        u64 m1A = 0ull, m1B = 0ull;
        #pragma unroll
        for (int p = 0; p < 32; p++) {
            float lo, hi;
            unpack2(hA[p], lo, hi);
            lo = fmaxf(lo, 0.0f); hi = fmaxf(hi, 0.0f);
            if (lo > 0.0f) m1A |= 1ull << (2*p);
            if (hi > 0.0f) m1A |= 1ull << (2*p+1);
            hA[p] = pack2(lo, hi);
            unpack2(hB[p], lo, hi);
            lo = fmaxf(lo, 0.0f); hi = fmaxf(hi, 0.0f);
            if (lo > 0.0f) m1B |= 1ull << (2*p);
            if (hi > 0.0f) m1B |= 1ull << (2*p+1);
            hB[p] = pack2(lo, hi);
        }

        // ============ layer 2: only sign(h @ W2 + b2) is needed ============
        u64 m2A = 0ull, m2B = 0ull;
        #pragma unroll 1
        for (int j = 0; j < 64; j++) {
            const ulonglong2* row =
                reinterpret_cast<const ulonglong2*>(sW2T + j * 64);
            u64 a0 = 0ull, a1 = 0ull, b0 = 0ull, b1 = 0ull;
            #pragma unroll
            for (int e = 0; e < 16; e++) {
                const ulonglong2 w = row[e];
                a0 = fma2(hA[2*e],   w.x, a0);
                a1 = fma2(hA[2*e+1], w.y, a1);
                b0 = fma2(hB[2*e],   w.x, b0);
                b1 = fma2(hB[2*e+1], w.y, b1);
            }
            const float bj = sb2[j];
            float lo, hi;
            unpack2(add2(a0, a1), lo, hi);
            if ((lo + hi) + bj > 0.0f) m2A |= 1ull << j;
            unpack2(add2(b0, b1), lo, hi);
            if ((lo + hi) + bj > 0.0f) m2B |= 1ull << j;
        }

        // ===== t = W2 @ d2, d2_j = (m2_j ? W3_j : 0); h banks are dead =====
        u64 tA[32], tB[32];
        #pragma unroll
        for (int p = 0; p < 32; p++) { tA[p] = 0ull; tB[p] = 0ull; }
        #pragma unroll 1
        for (int j = 0; j < 64; j++) {
            const float w3 = sW3[j];
            const float dA = ((m2A >> j) & 1ull) ? w3 : 0.0f;
            const float dB = ((m2B >> j) & 1ull) ? w3 : 0.0f;
            const u64 dpA = pack2(dA, dA);
            const u64 dpB = pack2(dB, dB);
            const ulonglong2* row =
                reinterpret_cast<const ulonglong2*>(sW2T + j * 64);
            #pragma unroll
            for (int e = 0; e < 16; e++) {
                const ulonglong2 w = row[e];
                tA[2*e]   = fma2(dpA, w.x, tA[2*e]);
                tA[2*e+1] = fma2(dpA, w.y, tA[2*e+1]);
                tB[2*e]   = fma2(dpB, w.x, tB[2*e]);
                tB[2*e+1] = fma2(dpB, w.y, tB[2*e+1]);
            }
        }

        // gate by layer-1 masks; fold output negation in here
        #pragma unroll
        for (int p = 0; p < 32; p++) {
            float lo, hi;
            unpack2(tA[p], lo, hi);
            lo = ((m1A >> (2*p))   & 1ull) ? -lo : 0.0f;
            hi = ((m1A >> (2*p+1)) & 1ull) ? -hi : 0.0f;
            tA[p] = pack2(lo, hi);
            unpack2(tB[p], lo, hi);
            lo = ((m1B >> (2*p))   & 1ull) ? -lo : 0.0f;
            hi = ((m1B >> (2*p+1)) & 1ull) ? -hi : 0.0f;
            tB[p] = pack2(lo, hi);
        }

        // ========= out_i = W1[i,:] . tgated  (i < 32, q rows only) =========
        float* oA = out + (size_t)sA * 32;
        float* oB = out + (size_t)sB * 32;
        #pragma unroll 1
        for (int i = 0; i < 32; i += 2) {
            const ulonglong2* r0 =
                reinterpret_cast<const ulonglong2*>(sW1 + i * 64);
            const ulonglong2* r1 = r0 + 16;
            u64 aA0 = 0ull, aA1 = 0ull, aB0 = 0ull, aB1 = 0ull;
            u64 cA0 = 0ull, cA1 = 0ull, cB0 = 0ull, cB1 = 0ull;
            #pragma unroll
            for (int e = 0; e < 16; e++) {
                const ulonglong2 w0 = r0[e];
                const ulonglong2 w1 = r1[e];
                aA0 = fma2(tA[2*e],   w0.x, aA0);
                aA1 = fma2(tA[2*e+1], w0.y, aA1);
                aB0 = fma2(tB[2*e],   w0.x, aB0);
                aB1 = fma2(tB[2*e+1], w0.y, aB1);
                cA0 = fma2(tA[2*e],   w1.x, cA0);
                cA1 = fma2(tA[2*e+1], w1.y, cA1);
                cB0 = fma2(tB[2*e],   w1.x, cB0);
                cB1 = fma2(tB[2*e+1], w1.y, cB1);
            }
            float lo, hi;
            float2 rA, rB;
            unpack2(add2(aA0, aA1), lo, hi); rA.x = lo + hi;
            unpack2(add2(cA0, cA1), lo, hi); rA.y = lo + hi;
            unpack2(add2(aB0, aB1), lo, hi); rB.x = lo + hi;
            unpack2(add2(cB0, cB1), lo, hi); rB.y = lo + hi;
            reinterpret_cast<float2*>(oA)[i >> 1] = rA;
            if (bval) reinterpret_cast<float2*>(oB)[i >> 1] = rB;
        }
    }
}

extern "C" void kernel_launch(void* const* d_in, const int* in_sizes, int n_in,
                              void* d_out, int out_size)
{
    const float* X  = (const float*)d_in[0];
    const float* W1 = (const float*)d_in[1];
    const float* b1 = (const float*)d_in[2];
    const float* W2 = (const float*)d_in[3];
    const float* b2 = (const float*)d_in[4];
    const float* W3 = (const float*)d_in[5];
    float* out = (float*)d_out;

    const int B = in_sizes[0] / 64;
    int grid = 148 * 3;                       // persistent: 3 blocks/SM
    const int maxg = (B + 255) / 256;
    if (grid > maxg) grid = maxg;
    lnn_kernel<<<grid, 128>>>(X, W1, b1, W2, b2, W3, out, B);
}

// round 7
// speedup vs baseline: 5.0584x; 5.0584x over previous
#include <cuda_runtime.h>
#include <cuda_fp16.h>
#include <cstdint>

// LNN Euler-Lagrange residual: ReLU MLP => grad-of-grad vanishes under
// autodiff; output is exactly -dL/dq.
//
// Tensor-core chain with portable mma.sync.m16n8k16 (HMMA; tcgen05 is
// unavailable because the harness emits .target sm_103 without 'a').
// Per warp, per 32 rows of a 128-sample tile:
//   GEMM1: PRE1 = X  @ W1    (epilogue: +b1, relu, mask1)
//   GEMM2: PRE2 = H  @ W2    (epilogue: +b2, sign -> d2 = mask2 * W3)
//   GEMM3: T    = D2 @ W2^T  (epilogue: gate by mask1, negate)
//   GEMM4: OUT  = D1 @ W1[0:32,:]^T  (direct STG)
// C-fragment (row,col) ownership == A-fragment (row,k) ownership for
// m16n8k16, so each GEMM's output converts to the next GEMM's A operand
// entirely in registers: no smem round trips, no syncs in the main loop.
// fp16 hi/lo split (3 mma per logical MAC tile) keeps ~1e-6 product error.

typedef uint32_t u32;

__device__ __forceinline__ u32 smem_addr(const void* p) {
    u32 a;
    asm("{ .reg .u64 t; cvta.to.shared.u64 t, %1; cvt.u32.u64 %0, t; }"
        : "=r"(a) : "l"(p));
    return a;
}
__device__ __forceinline__ u32 pack_f16x2(float x0, float x1) {   // lo=x0, hi=x1
    u32 r; asm("cvt.rn.f16x2.f32 %0, %1, %2;" : "=r"(r) : "f"(x1), "f"(x0));
    return r;
}
__device__ __forceinline__ float2 unpack_h2(u32 v) {
    float2 r;
    asm("{ .reg .b16 lo1, hi1; mov.b32 {lo1, hi1}, %2; "
        "cvt.f32.f16 %0, lo1; cvt.f32.f16 %1, hi1; }"
        : "=f"(r.x), "=f"(r.y) : "r"(v));
    return r;
}
// fp32 pair -> fp16 hi word + fp16 residual word
__device__ __forceinline__ void split2(float x0, float x1, u32& hi, u32& lo) {
    hi = pack_f16x2(x0, x1);
    const float2 hf = unpack_h2(hi);
    lo = pack_f16x2(x0 - hf.x, x1 - hf.y);
}
__device__ __forceinline__ void ldm4(u32 r[4], u32 addr) {
    asm volatile("ldmatrix.sync.aligned.m8n8.x4.shared.b16 {%0,%1,%2,%3}, [%4];"
                 : "=r"(r[0]), "=r"(r[1]), "=r"(r[2]), "=r"(r[3]) : "r"(addr));
}
#define MMA(cc, aa, b0, b1)                                                  \
    asm volatile("mma.sync.aligned.m16n8k16.row.col.f32.f16.f16.f32 "        \
        "{%0,%1,%2,%3}, {%4,%5,%6,%7}, {%8,%9}, {%0,%1,%2,%3};"              \
        : "+f"((cc)[0]), "+f"((cc)[1]), "+f"((cc)[2]), "+f"((cc)[3])         \
        : "r"((aa)[0]), "r"((aa)[1]), "r"((aa)[2]), "r"((aa)[3]),            \
          "r"(b0), "r"(b1))

// smem: weight tiles stored [n][k] as fp16, row stride 72 halfs (144 B,
// rotates ldmatrix rows across banks -> conflict-free). hi and lo planes.
// Byte offsets:
#define OB_W1T_H 0
#define OB_W1T_L 9216
#define OB_W2T_H 18432
#define OB_W2T_L 27648
#define OB_W2_H  36864
#define OB_W2_L  46080
#define OB_W1Q_H 55296
#define OB_W1Q_L 59904
#define OB_B1    64512
#define OB_B2    64768
#define OB_W3    65024
#define SMEM_TOTAL 65280

template <int NT>
__device__ __forceinline__ void run_gemm(float (&c)[2][8][4],
                                         const u32 (&Ah)[2][4][4],
                                         const u32 (&Al)[2][4][4],
                                         u32 bh_base, u32 bl_base) {
    #pragma unroll
    for (int m = 0; m < 2; m++)
        #pragma unroll
        for (int nt = 0; nt < NT; nt++)
            #pragma unroll
            for (int q = 0; q < 4; q++) c[m][nt][q] = 0.0f;

    #pragma unroll
    for (int nt = 0; nt < NT; nt++) {
        #pragma unroll
        for (int ktp = 0; ktp < 2; ktp++) {
            u32 bh[4], bl[4];
            ldm4(bh, bh_base + nt * 1152 + ktp * 64);
            ldm4(bl, bl_base + nt * 1152 + ktp * 64);
            #pragma unroll
            for (int m = 0; m < 2; m++) {
                #pragma unroll
                for (int s = 0; s < 2; s++) {
                    const int kt = 2 * ktp + s;
                    MMA(c[m][nt], Ah[m][kt], bh[2*s], bh[2*s+1]);
                    MMA(c[m][nt], Ah[m][kt], bl[2*s], bl[2*s+1]);
                    MMA(c[m][nt], Al[m][kt], bh[2*s], bh[2*s+1]);
                }
            }
        }
    }
}

__global__ void __launch_bounds__(128, 2)
lnn_kernel(const float* __restrict__ X,
           const float* __restrict__ W1g, const float* __restrict__ b1g,
           const float* __restrict__ W2g, const float* __restrict__ b2g,
           const float* __restrict__ W3g,
           float* __restrict__ out, int B)
{
    extern __shared__ char smem[];
    __half* sh = reinterpret_cast<__half*>(smem);
    float* sb1 = reinterpret_cast<float*>(smem + OB_B1);
    float* sb2 = reinterpret_cast<float*>(smem + OB_B2);
    float* sw3 = reinterpret_cast<float*>(smem + OB_W3);

    const int tid = threadIdx.x;
    const int wid = tid >> 5, lane = tid & 31;
    const int g = lane >> 2, tig = lane & 3;

    // ---- one-time weight staging: fp16 hi/lo planes, [n][k] stride 72 ----
    for (int idx = tid; idx < 4096; idx += 128) {
        const int r = idx >> 6, cc = idx & 63;
        {
            const float v = W1g[idx];                         // W1[r][cc]
            const __half hh = __float2half_rn(v);
            const __half hl = __float2half_rn(v - __half2float(hh));
            sh[(OB_W1T_H >> 1) + cc * 72 + r] = hh;           // W1T[n=cc][k=r]
            sh[(OB_W1T_L >> 1) + cc * 72 + r] = hl;
            if (r < 32) {                                     // W1q[n=r][k=cc]
                sh[(OB_W1Q_H >> 1) + r * 72 + cc] = hh;
                sh[(OB_W1Q_L >> 1) + r * 72 + cc] = hl;
            }
        }
        {
            const float v = W2g[idx];                         // W2[r][cc]
            const __half hh = __float2half_rn(v);
            const __half hl = __float2half_rn(v - __half2float(hh));
            sh[(OB_W2T_H >> 1) + cc * 72 + r] = hh;           // W2T[n=cc][k=r]
            sh[(OB_W2T_L >> 1) + cc * 72 + r] = hl;
            sh[(OB_W2_H >> 1) + r * 72 + cc] = hh;            // W2[n=r][k=cc]
            sh[(OB_W2_L >> 1) + r * 72 + cc] = hl;
        }
    }
    if (tid < 64) { sb1[tid] = b1g[tid]; sb2[tid] = b2g[tid]; sw3[tid] = W3g[tid]; }
    __syncthreads();

    const u32 sbase = smem_addr(smem);
    const u32 laneoff = (lane & 7) * 144 + (lane >> 3) * 16;
    const u32 bW1T_h = sbase + OB_W1T_H + laneoff, bW1T_l = sbase + OB_W1T_L + laneoff;
    const u32 bW2T_h = sbase + OB_W2T_H + laneoff, bW2T_l = sbase + OB_W2T_L + laneoff;
    const u32 bW2_h  = sbase + OB_W2_H  + laneoff, bW2_l  = sbase + OB_W2_L  + laneoff;
    const u32 bW1Q_h = sbase + OB_W1Q_H + laneoff, bW1Q_l = sbase + OB_W1Q_L + laneoff;

    const int ntiles = (B + 127) >> 7;
    float c[2][8][4];
    u32 Ah[2][4][4], Al[2][4][4];

    for (int tile = blockIdx.x; tile < ntiles; tile += gridDim.x) {
        const int rowbase = tile * 128 + wid * 32;

        // ---- A = X fragments straight from gmem (fp32 -> hi/lo fp16) ----
        #pragma unroll
        for (int m = 0; m < 2; m++) {
            int r0 = rowbase + 16 * m + g;
            int r1 = r0 + 8;
            if (r0 >= B) r0 = B - 1;
            if (r1 >= B) r1 = B - 1;
            const float* x0 = X + (size_t)r0 * 64 + 2 * tig;
            const float* x1 = X + (size_t)r1 * 64 + 2 * tig;
            #pragma unroll
            for (int kt = 0; kt < 4; kt++) {
                const float2 v00 = *reinterpret_cast<const float2*>(x0 + 16*kt);
                const float2 v01 = *reinterpret_cast<const float2*>(x0 + 16*kt + 8);
                const float2 v10 = *reinterpret_cast<const float2*>(x1 + 16*kt);
                const float2 v11 = *reinterpret_cast<const float2*>(x1 + 16*kt + 8);
                split2(v00.x, v00.y, Ah[m][kt][0], Al[m][kt][0]);
                split2(v10.x, v10.y, Ah[m][kt][1], Al[m][kt][1]);
                split2(v01.x, v01.y, Ah[m][kt][2], Al[m][kt][2]);
                split2(v11.x, v11.y, Ah[m][kt][3], Al[m][kt][3]);
            }
        }

        // ================= GEMM1: PRE1 = X @ W1 =================
        run_gemm<8>(c, Ah, Al, bW1T_h, bW1T_l);
        u32 m1[2] = {0u, 0u};
        #pragma unroll
        for (int m = 0; m < 2; m++) {
            #pragma unroll
            for (int nt = 0; nt < 8; nt++) {
                const float2 bv = *reinterpret_cast<const float2*>(sb1 + 8*nt + 2*tig);
                float p0 = c[m][nt][0] + bv.x;
                float p1 = c[m][nt][1] + bv.y;
                float p2 = c[m][nt][2] + bv.x;
                float p3 = c[m][nt][3] + bv.y;
                if (p0 > 0.0f) m1[m] |= 1u << (4*nt + 0); else p0 = 0.0f;
                if (p1 > 0.0f) m1[m] |= 1u << (4*nt + 1); else p1 = 0.0f;
                if (p2 > 0.0f) m1[m] |= 1u << (4*nt + 2); else p2 = 0.0f;
                if (p3 > 0.0f) m1[m] |= 1u << (4*nt + 3); else p3 = 0.0f;
                const int kt = nt >> 1, o = (nt & 1) << 1;
                split2(p0, p1, Ah[m][kt][o],     Al[m][kt][o]);
                split2(p2, p3, Ah[m][kt][o + 1], Al[m][kt][o + 1]);
            }
        }

        // ================= GEMM2: PRE2 = H @ W2 =================
        run_gemm<8>(c, Ah, Al, bW2T_h, bW2T_l);
        #pragma unroll
        for (int m = 0; m < 2; m++) {
            #pragma unroll
            for (int nt = 0; nt < 8; nt++) {
                const float2 bv = *reinterpret_cast<const float2*>(sb2 + 8*nt + 2*tig);
                const float2 wv = *reinterpret_cast<const float2*>(sw3 + 8*nt + 2*tig);
                const float d0 = (c[m][nt][0] + bv.x > 0.0f) ? wv.x : 0.0f;
                const float d1 = (c[m][nt][1] + bv.y > 0.0f) ? wv.y : 0.0f;
                const float d2 = (c[m][nt][2] + bv.x > 0.0f) ? wv.x : 0.0f;
                const float d3 = (c[m][nt][3] + bv.y > 0.0f) ? wv.y : 0.0f;
                const int kt = nt >> 1, o = (nt & 1) << 1;
                split2(d0, d1, Ah[m][kt][o],     Al[m][kt][o]);
                split2(d2, d3, Ah[m][kt][o + 1], Al[m][kt][o + 1]);
            }
        }

        // ================= GEMM3: T = D2 @ W2^T =================
        run_gemm<8>(c, Ah, Al, bW2_h, bW2_l);
        #pragma unroll
        for (int m = 0; m < 2; m++) {
            #pragma unroll
            for (int nt = 0; nt < 8; nt++) {
                const float t0 = ((m1[m] >> (4*nt + 0)) & 1u) ? -c[m][nt][0] : 0.0f;
                const float t1 = ((m1[m] >> (4*nt + 1)) & 1u) ? -c[m][nt][1] : 0.0f;
                const float t2 = ((m1[m] >> (4*nt + 2)) & 1u) ? -c[m][nt][2] : 0.0f;
                const float t3 = ((m1[m] >> (4*nt + 3)) & 1u) ? -c[m][nt][3] : 0.0f;
                const int kt = nt >> 1, o = (nt & 1) << 1;
                split2(t0, t1, Ah[m][kt][o],     Al[m][kt][o]);
                split2(t2, t3, Ah[m][kt][o + 1], Al[m][kt][o + 1]);
            }
        }

        // ============ GEMM4: OUT = D1 @ W1q^T (N = 32) ============
        run_gemm<4>(c, Ah, Al, bW1Q_h, bW1Q_l);
        #pragma unroll
        for (int m = 0; m < 2; m++) {
            const int r0 = rowbase + 16 * m + g;
            const int r1 = r0 + 8;
            #pragma unroll
            for (int nt = 0; nt < 4; nt++) {
                const int col = 8 * nt + 2 * tig;
                if (r0 < B)
                    *reinterpret_cast<float2*>(out + (size_t)r0 * 32 + col) =
                        make_float2(c[m][nt][0], c[m][nt][1]);
                if (r1 < B)
                    *reinterpret_cast<float2*>(out + (size_t)r1 * 32 + col) =
                        make_float2(c[m][nt][2], c[m][nt][3]);
            }
        }
    }
}

extern "C" void kernel_launch(void* const* d_in, const int* in_sizes, int n_in,
                              void* d_out, int out_size)
{
    const float* X  = (const float*)d_in[0];
    const float* W1 = (const float*)d_in[1];
    const float* b1 = (const float*)d_in[2];
    const float* W2 = (const float*)d_in[3];
    const float* b2 = (const float*)d_in[4];
    const float* W3 = (const float*)d_in[5];
    float* out = (float*)d_out;

    const int B = in_sizes[0] / 64;
    const int ntiles = (B + 127) / 128;
    int grid = 148 * 2;                 // persistent, 2 CTAs/SM
    if (grid > ntiles) grid = ntiles;

    cudaFuncSetAttribute(lnn_kernel,
                         cudaFuncAttributeMaxDynamicSharedMemorySize,
                         SMEM_TOTAL);
    lnn_kernel<<<grid, 128, SMEM_TOTAL>>>(X, W1, b1, W2, b2, W3, out, B);
}